// round 1
// baseline (speedup 1.0000x reference)
#include <cuda_runtime.h>
#include <math.h>

// ---- problem constants (fixed by the dataset) ----
#define B_IMG   32
#define NAN_C   3          // num anchors per cell
#define GRID    52
#define A_PER   (NAN_C * GRID * GRID)   // 8112 anchors per image
#define M_GT    50
#define C_CLS   80
#define STRIDE_F 8.0f
#define EPS_F   1e-7f

#define BLOCK   256
#define BLOCKS_PER_IMG ((A_PER + BLOCK - 1) / BLOCK)   // 32
#define NBLK    (B_IMG * BLOCKS_PER_IMG)               // 1024

// per-block partials: x=cls, y=reg, z=conf
__device__ float4 g_part[NBLK];

__global__ __launch_bounds__(BLOCK)
void yolo_main_kernel(const float* __restrict__ pred,
                      const float* __restrict__ bbox)
{
    __shared__ float4 s_box[M_GT];   // x1,y1,x2,y2
    __shared__ float  s_area[M_GT];  // w*h (0 if invalid)
    __shared__ float4 s_raw[M_GT];   // cx,cy,w,h
    __shared__ float  s_cls[M_GT];

    const int img = blockIdx.x >> 5;        // /BLOCKS_PER_IMG (=32)
    const int blk = blockIdx.x & 31;
    const int tid = threadIdx.x;

    // ---- GT preprocessing (threads 0..49) ----
    if (tid < M_GT) {
        const float* g = bbox + (size_t)(img * M_GT + tid) * 5;
        float x = g[0], y = g[1], w = g[2], h = g[3], c = g[4];
        bool valid = (c != -1.0f);
        float cx = x + 0.5f * w;
        float cy = y + 0.5f * h;
        float x1 = cx - 0.5f * w, x2 = cx + 0.5f * w;
        float y1 = cy - 0.5f * h, y2 = cy + 0.5f * h;
        if (!valid) {            // degenerate box -> inter = 0 always
            x1 = 1e30f; y1 = 1e30f; x2 = -1e30f; y2 = -1e30f;
        }
        s_box[tid]  = make_float4(x1, y1, x2, y2);
        s_area[tid] = valid ? (w * h) : 0.0f;
        s_raw[tid]  = make_float4(cx, cy, w, h);
        s_cls[tid]  = c;
    }
    __syncthreads();

    float cls_sum = 0.0f, reg_sum = 0.0f, conf_sum = 0.0f;

    const int aidx = blk * BLOCK + tid;
    if (aidx < A_PER) {
        // anchor geometry from index (exact match with reference anchors)
        const int a   = aidx / (GRID * GRID);
        const int rem = aidx - a * (GRID * GRID);
        const int gy  = rem / GRID;
        const int gx  = rem - gy * GRID;
        const float aw = (a == 0) ? 10.0f : ((a == 1) ? 16.0f : 33.0f);
        const float ah = (a == 0) ? 13.0f : ((a == 1) ? 30.0f : 23.0f);
        const float acx = ((float)gx + 0.5f) * STRIDE_F;
        const float acy = ((float)gy + 0.5f) * STRIDE_F;
        const float ax1 = acx - 0.5f * aw, ax2 = acx + 0.5f * aw;
        const float ay1 = acy - 0.5f * ah, ay2 = acy + 0.5f * ah;
        const float sa  = aw * ah;

        // ---- IoU argmax over 50 GTs, division-free (cross-multiplication) ----
        float b_inter = -1.0f;   // encodes iou = -1 for "nothing yet"
        float b_den   = 1.0f;
        int   b_idx   = 0;
        #pragma unroll 10
        for (int j = 0; j < M_GT; j++) {
            float4 bb = s_box[j];
            float iw = fminf(ax2, bb.z) - fmaxf(ax1, bb.x);
            float ih = fminf(ay2, bb.w) - fmaxf(ay1, bb.y);
            iw = fmaxf(iw, 0.0f);
            ih = fmaxf(ih, 0.0f);
            float inter = iw * ih;
            float den   = sa + s_area[j] - inter;   // > 0 always
            // inter/den > b_inter/b_den  <=>  inter*b_den > b_inter*den
            if (inter * b_den > b_inter * den) {
                b_inter = inter; b_den = den; b_idx = j;
            }
        }
        const bool pos = (2.0f * b_inter >= b_den);   // iou >= 0.5

        const float* p = pred + (size_t)(img * A_PER + aidx) * (C_CLS + 5);

        // ---- confidence MSE ----
        {
            float cf = p[4];
            conf_sum = pos ? (cf - 1.0f) * (cf - 1.0f) : 0.5f * cf * cf;
        }

        // ---- classification BCE: base term -sum log(1-p) via log-of-product ----
        float l2sum = 0.0f;
        #pragma unroll
        for (int grp = 0; grp < 5; grp++) {
            float prod = 1.0f;
            #pragma unroll
            for (int k = 0; k < 16; k++) {
                float pc = p[5 + grp * 16 + k];
                pc = fminf(fmaxf(pc, EPS_F), 1.0f - EPS_F);
                prod *= (1.0f - pc);
            }
            l2sum += __log2f(prod);
        }
        cls_sum = -0.69314718055994530942f * l2sum;   // -sum ln(1-p)

        // ---- positive anchor: one-hot correction + regression ----
        if (pos) {
            int c = (int)s_cls[b_idx];
            float pc = p[5 + c];
            pc = fminf(fmaxf(pc, EPS_F), 1.0f - EPS_F);
            // swap -log(1-pc) (already counted) for -log(pc)
            cls_sum += __logf(1.0f - pc) - __logf(pc);

            float4 r = s_raw[b_idx];
            float gxx = r.x * 0.125f, gyy = r.y * 0.125f;     // /stride (exact)
            float gw  = fmaxf(r.z, 1.0f), gh = fmaxf(r.w, 1.0f);
            float acxs = acx * 0.125f, acys = acy * 0.125f;

            float r0 = p[0], r1 = p[1], r2 = p[2], r3 = p[3];
            float stx  = 1.0f / (1.0f + __expf(-r0));
            float sty  = 1.0f / (1.0f + __expf(-r1));
            float stxg = 1.0f / (1.0f + __expf(-(gxx - acxs)));
            float styg = 1.0f / (1.0f + __expf(-(gyy - acys)));
            float twg = __logf(gw / aw + 1e-16f);
            float thg = __logf(gh / ah + 1e-16f);
            float param = 2.0f - fabsf(twg) * fabsf(thg);
            float dx = stx - stxg, dy = sty - styg;
            float dw = r2 - twg,   dh = r3 - thg;
            reg_sum = 5.0f * param * (dx * dx + dy * dy + dw * dw + dh * dh);
        }
    }

    // ---- deterministic block reduction (shuffle + smem) ----
    #pragma unroll
    for (int off = 16; off > 0; off >>= 1) {
        cls_sum  += __shfl_down_sync(0xffffffffu, cls_sum,  off);
        reg_sum  += __shfl_down_sync(0xffffffffu, reg_sum,  off);
        conf_sum += __shfl_down_sync(0xffffffffu, conf_sum, off);
    }
    __shared__ float3 s_red[BLOCK / 32];
    const int wid = tid >> 5, lane = tid & 31;
    if (lane == 0) s_red[wid] = make_float3(cls_sum, reg_sum, conf_sum);
    __syncthreads();
    if (tid == 0) {
        float3 t = s_red[0];
        #pragma unroll
        for (int i = 1; i < BLOCK / 32; i++) {
            t.x += s_red[i].x; t.y += s_red[i].y; t.z += s_red[i].z;
        }
        g_part[blockIdx.x] = make_float4(t.x, t.y, t.z, 0.0f);
    }
}

__global__ __launch_bounds__(256)
void yolo_reduce_kernel(float* __restrict__ out)
{
    __shared__ double sc[256], sr[256], sf[256];
    const int tid = threadIdx.x;
    double c = 0.0, r = 0.0, f = 0.0;
    for (int i = tid; i < NBLK; i += 256) {
        float4 v = g_part[i];
        c += (double)v.x; r += (double)v.y; f += (double)v.z;
    }
    sc[tid] = c; sr[tid] = r; sf[tid] = f;
    __syncthreads();
    for (int s = 128; s > 0; s >>= 1) {
        if (tid < s) {
            sc[tid] += sc[tid + s];
            sr[tid] += sr[tid + s];
            sf[tid] += sf[tid + s];
        }
        __syncthreads();
    }
    if (tid == 0) {
        const double inv = 1.0 / (double)B_IMG;
        out[0] = (float)(sc[0] * inv);   // cls mean
        out[1] = (float)(sr[0] * inv);   // reg mean
        out[2] = (float)(sf[0] * inv);   // conf mean
    }
}

extern "C" void kernel_launch(void* const* d_in, const int* in_sizes, int n_in,
                              void* d_out, int out_size)
{
    const float* pred = (const float*)d_in[0];   // (32,3,52,52,85)
    const float* bbox = (const float*)d_in[1];   // (32,50,5)
    (void)in_sizes; (void)n_in; (void)out_size;

    yolo_main_kernel<<<NBLK, BLOCK>>>(pred, bbox);
    yolo_reduce_kernel<<<1, 256>>>((float*)d_out);
}

// round 2
// speedup vs baseline: 1.3394x; 1.3394x over previous
#include <cuda_runtime.h>
#include <math.h>

// ---- problem constants (fixed by the dataset) ----
#define B_IMG   32
#define GRID    52
#define A_PER   (3 * GRID * GRID)       // 8112 anchors per image
#define M_GT    50
#define C_CLS   80
#define ROW_F   85                      // floats per anchor row
#define EPS_F   1e-7f

#define BLOCK   128
#define WARPS   (BLOCK / 32)
#define BPI     64                      // ceil(8112/128)
#define NBLK    (B_IMG * BPI)           // 2048

#define TILE_F     (32 * ROW_F)         // 2720 floats per warp tile
#define TILE_F4    (TILE_F / 4)         // 680
#define TOT_F4     ((size_t)B_IMG * A_PER * ROW_F / 4)

// per-block partials: x=cls, y=reg, z=conf
__device__ float4 g_part[NBLK];
__device__ unsigned int g_count = 0;

__global__ __launch_bounds__(BLOCK)
void yolo_fused_kernel(const float* __restrict__ pred,
                       const float* __restrict__ bbox,
                       float* __restrict__ out)
{
    __shared__ float  s_pred[WARPS * TILE_F];   // 43,520 B
    __shared__ float4 s_box[M_GT];              // x1,y1,x2,y2
    __shared__ float  s_area[M_GT];
    __shared__ float4 s_raw[M_GT];              // cx,cy,w,h
    __shared__ float  s_cls[M_GT];

    const int img  = blockIdx.x >> 6;           // / BPI
    const int blk  = blockIdx.x & 63;
    const int tid  = threadIdx.x;
    const int wid  = tid >> 5;
    const int lane = tid & 31;

    // ---- GT preprocessing (threads 0..49) ----
    if (tid < M_GT) {
        const float* g = bbox + (size_t)(img * M_GT + tid) * 5;
        float x = g[0], y = g[1], w = g[2], h = g[3], c = g[4];
        bool valid = (c != -1.0f);
        float cx = x + 0.5f * w;
        float cy = y + 0.5f * h;
        float x1 = cx - 0.5f * w, x2 = cx + 0.5f * w;
        float y1 = cy - 0.5f * h, y2 = cy + 0.5f * h;
        if (!valid) { x1 = 1e30f; y1 = 1e30f; x2 = -1e30f; y2 = -1e30f; }
        s_box[tid]  = make_float4(x1, y1, x2, y2);
        s_area[tid] = valid ? (w * h) : 0.0f;
        s_raw[tid]  = make_float4(cx, cy, w, h);
        s_cls[tid]  = c;
    }

    // ---- warp-cooperative staged load: 680 coalesced float4 per warp ----
    const int tile_anchor = blk * BLOCK + wid * 32;            // first anchor of tile
    const size_t f4base = ((size_t)(img * A_PER + tile_anchor) * ROW_F) >> 2;
    const float4* __restrict__ gp4 = (const float4*)pred;
    float4* s4 = (float4*)(s_pred + wid * TILE_F);
    #pragma unroll
    for (int k = 0; k < 21; k++) {
        int idx = k * 32 + lane;
        size_t g = f4base + idx;
        if (g >= TOT_F4) g = TOT_F4 - 1;   // clamp (only img 31 tail tiles)
        s4[idx] = gp4[g];
    }
    if (lane < 8) {
        int idx = 672 + lane;
        size_t g = f4base + idx;
        if (g >= TOT_F4) g = TOT_F4 - 1;
        s4[idx] = gp4[g];
    }
    __syncwarp();
    __syncthreads();   // GT smem ready (also covers staging)

    float cls_sum = 0.0f, reg_sum = 0.0f, conf_sum = 0.0f;

    const int aidx = tile_anchor + lane;
    if (aidx < A_PER) {
        // anchor geometry from index
        const int a   = aidx / (GRID * GRID);
        const int rem = aidx - a * (GRID * GRID);
        const int gy  = rem / GRID;
        const int gx  = rem - gy * GRID;
        const float aw = (a == 0) ? 10.0f : ((a == 1) ? 16.0f : 33.0f);
        const float ah = (a == 0) ? 13.0f : ((a == 1) ? 30.0f : 23.0f);
        const float acx = ((float)gx + 0.5f) * 8.0f;
        const float acy = ((float)gy + 0.5f) * 8.0f;
        const float ax1 = acx - 0.5f * aw, ax2 = acx + 0.5f * aw;
        const float ay1 = acy - 0.5f * ah, ay2 = acy + 0.5f * ah;
        const float sa  = aw * ah;

        // ---- division-free IoU argmax over 50 GTs ----
        float b_inter = -1.0f, b_den = 1.0f;
        int   b_idx = 0;
        #pragma unroll 10
        for (int j = 0; j < M_GT; j++) {
            float4 bb = s_box[j];
            float iw = fmaxf(fminf(ax2, bb.z) - fmaxf(ax1, bb.x), 0.0f);
            float ih = fmaxf(fminf(ay2, bb.w) - fmaxf(ay1, bb.y), 0.0f);
            float inter = iw * ih;
            float den   = sa + s_area[j] - inter;
            if (inter * b_den > b_inter * den) {
                b_inter = inter; b_den = den; b_idx = j;
            }
        }
        const bool pos = (2.0f * b_inter >= b_den);   // iou >= 0.5

        const float* row = s_pred + wid * TILE_F + lane * ROW_F;

        // ---- confidence MSE ----
        {
            float cf = row[4];
            conf_sum = pos ? (cf - 1.0f) * (cf - 1.0f) : 0.5f * cf * cf;
        }

        // ---- classification BCE base: -sum ln(1-p) via log-of-product ----
        float l2sum = 0.0f;
        #pragma unroll
        for (int grp = 0; grp < 5; grp++) {
            float prod = 1.0f;
            #pragma unroll
            for (int k = 0; k < 16; k++) {
                float pc = row[5 + grp * 16 + k];
                pc = fminf(fmaxf(pc, EPS_F), 1.0f - EPS_F);
                prod *= (1.0f - pc);
            }
            l2sum += __log2f(prod);
        }
        cls_sum = -0.69314718055994530942f * l2sum;

        // ---- positive anchor: one-hot correction + regression ----
        if (pos) {
            int c = (int)s_cls[b_idx];
            float pc = row[5 + c];
            pc = fminf(fmaxf(pc, EPS_F), 1.0f - EPS_F);
            cls_sum += __logf(1.0f - pc) - __logf(pc);

            float4 r = s_raw[b_idx];
            float gxx = r.x * 0.125f, gyy = r.y * 0.125f;
            float gw  = fmaxf(r.z, 1.0f), gh = fmaxf(r.w, 1.0f);
            float acxs = acx * 0.125f, acys = acy * 0.125f;

            float r0 = row[0], r1 = row[1], r2 = row[2], r3 = row[3];
            float stx  = 1.0f / (1.0f + __expf(-r0));
            float sty  = 1.0f / (1.0f + __expf(-r1));
            float stxg = 1.0f / (1.0f + __expf(-(gxx - acxs)));
            float styg = 1.0f / (1.0f + __expf(-(gyy - acys)));
            float twg = __logf(gw / aw + 1e-16f);
            float thg = __logf(gh / ah + 1e-16f);
            float param = 2.0f - fabsf(twg) * fabsf(thg);
            float dx = stx - stxg, dy = sty - styg;
            float dw = r2 - twg,   dh = r3 - thg;
            reg_sum = 5.0f * param * (dx * dx + dy * dy + dw * dw + dh * dh);
        }
    }

    // ---- deterministic block reduction ----
    #pragma unroll
    for (int off = 16; off > 0; off >>= 1) {
        cls_sum  += __shfl_down_sync(0xffffffffu, cls_sum,  off);
        reg_sum  += __shfl_down_sync(0xffffffffu, reg_sum,  off);
        conf_sum += __shfl_down_sync(0xffffffffu, conf_sum, off);
    }
    __shared__ float3 s_red[WARPS];
    if (lane == 0) s_red[wid] = make_float3(cls_sum, reg_sum, conf_sum);
    __syncthreads();

    __shared__ bool s_last;
    if (tid == 0) {
        float3 t = s_red[0];
        #pragma unroll
        for (int i = 1; i < WARPS; i++) {
            t.x += s_red[i].x; t.y += s_red[i].y; t.z += s_red[i].z;
        }
        g_part[blockIdx.x] = make_float4(t.x, t.y, t.z, 0.0f);
        __threadfence();
        unsigned int prev = atomicAdd(&g_count, 1u);
        s_last = (prev == NBLK - 1);
    }
    __syncthreads();

    // ---- last block performs the final deterministic reduce ----
    if (s_last) {
        double c = 0.0, rr = 0.0, f = 0.0;
        #pragma unroll
        for (int k = 0; k < NBLK / BLOCK; k++) {
            float4 v = g_part[k * BLOCK + tid];
            c += (double)v.x; rr += (double)v.y; f += (double)v.z;
        }
        __shared__ double sc[BLOCK], sr[BLOCK], sf[BLOCK];
        sc[tid] = c; sr[tid] = rr; sf[tid] = f;
        __syncthreads();
        for (int s = BLOCK / 2; s > 0; s >>= 1) {
            if (tid < s) {
                sc[tid] += sc[tid + s];
                sr[tid] += sr[tid + s];
                sf[tid] += sf[tid + s];
            }
            __syncthreads();
        }
        if (tid == 0) {
            const double inv = 1.0 / (double)B_IMG;
            out[0] = (float)(sc[0] * inv);
            out[1] = (float)(sr[0] * inv);
            out[2] = (float)(sf[0] * inv);
            g_count = 0;   // reset for next graph replay
        }
    }
}

extern "C" void kernel_launch(void* const* d_in, const int* in_sizes, int n_in,
                              void* d_out, int out_size)
{
    const float* pred = (const float*)d_in[0];   // (32,3,52,52,85)
    const float* bbox = (const float*)d_in[1];   // (32,50,5)
    (void)in_sizes; (void)n_in; (void)out_size;

    yolo_fused_kernel<<<NBLK, BLOCK>>>(pred, bbox, (float*)d_out);
}